// round 14
// baseline (speedup 1.0000x reference)
#include <cuda_runtime.h>
#include <cuda_fp16.h>
#include <cstdint>
#include <math.h>

#define B_   8
#define T_   4096
#define W_   1024
#define H_   8
#define NCH  4      // chunks per batch (1024 steps each)
#define CHL  1024
#define ITERS 16

// ---------------- scratch ----------------
__device__ __half g_Ph [(size_t)B_ * T_ * W_];   // chunk prefix products (fp16)
__device__ __half g_Ylh[(size_t)B_ * T_ * W_];   // chunk-local y (fp16, c>0 only)
__device__ float  g_Aprod[B_ * NCH * W_];
__device__ float  g_hlast[B_ * NCH * W_];

// ---------------- smem layout (bytes) ----------------
#define SP        66
#define SM_W      0                         // 2 x 16384 (fp16 w1,w2 half-cols)
#define SM_XH     32768                     // 2 x 16384 double-buffered
#define SM_SA     65536                     // 64*66*4 = 16896
#define SM_SNX    82432                     // 16896
#define SM_SC     99328                     // 256
#define SM_B1     99584
#define SM_B2     99840
#define SM_SEGA   100096                    // 8*64*4 = 2048
#define SM_SEGH   102144
#define SM_HRUN   104192                    // 2*64*4 parity
#define SM_PRUN   104704
#define SM_TOTAL  105216

__device__ __forceinline__ uint32_t smem_u32(const void* p) {
    uint32_t a;
    asm("{ .reg .u64 t; cvta.to.shared.u64 t, %1; cvt.u32.u64 %0, t; }" : "=r"(a) : "l"(p));
    return a;
}
__device__ __forceinline__ uint32_t swz256(uint32_t o) {
    return o ^ (((o >> 8) & 7u) << 4);
}
__device__ __forceinline__ uint32_t swz128(uint32_t o) {
    return o ^ ((o >> 3) & 0x70u);
}
__device__ __forceinline__ void ldm_x4(uint32_t* r, uint32_t addr) {
    asm volatile("ldmatrix.sync.aligned.m8n8.x4.shared.b16 {%0,%1,%2,%3}, [%4];"
        : "=r"(r[0]), "=r"(r[1]), "=r"(r[2]), "=r"(r[3]) : "r"(addr));
}
__device__ __forceinline__ void ldm_x4_t(uint32_t* r, uint32_t addr) {
    asm volatile("ldmatrix.sync.aligned.m8n8.x4.trans.shared.b16 {%0,%1,%2,%3}, [%4];"
        : "=r"(r[0]), "=r"(r[1]), "=r"(r[2]), "=r"(r[3]) : "r"(addr));
}
__device__ __forceinline__ void mma_f16(float* c, const uint32_t* a, const uint32_t* b) {
    asm volatile("mma.sync.aligned.m16n8k16.row.col.f32.f16.f16.f32 "
        "{%0,%1,%2,%3}, {%4,%5,%6,%7}, {%8,%9}, {%0,%1,%2,%3};"
        : "+f"(c[0]), "+f"(c[1]), "+f"(c[2]), "+f"(c[3])
        : "r"(a[0]), "r"(a[1]), "r"(a[2]), "r"(a[3]), "r"(b[0]), "r"(b[1]));
}
__device__ __forceinline__ float sigm(float v) {
    float t;
    asm("tanh.approx.f32 %0, %1;" : "=f"(t) : "f"(v * 0.5f));
    return fmaf(0.5f, t, 0.5f);
}
__device__ __forceinline__ float sqrt_ap(float v) {
    float r; asm("sqrt.approx.f32 %0, %1;" : "=f"(r) : "f"(v)); return r;
}
__device__ __forceinline__ uint32_t packh2(float a, float b) {
    __half2 t; t.x = __float2half_rn(a); t.y = __float2half_rn(b);
    return *(uint32_t*)&t;
}

// ---------------------------------------------------------------------------
// gates GEMM + fused scan. block = (chunk, head-half). 256 threads, 2 CTAs/SM.
// Double-buffered XH: 2 barriers/iteration.
// ---------------------------------------------------------------------------
__global__ void __launch_bounds__(256, 2) gates_kernel(
    const float* __restrict__ x, const float* __restrict__ w_in,
    const float* __restrict__ b_in, const float* __restrict__ w_a,
    const float* __restrict__ b_a, const float* __restrict__ a_param,
    float* __restrict__ y)
{
    extern __shared__ char sm[];
    const int tid = threadIdx.x, wid = tid >> 5, lane = tid & 31;
    const int h = blockIdx.y >> 1, half = blockIdx.y & 1;
    const int bx = blockIdx.x;                 // b*NCH + chunk
    const int c  = bx & (NCH - 1);
    const int row0 = bx * CHL;
    const int col0 = h * 128 + half * 64;

    float* scv  = (float*)(sm + SM_SC);
    float* b1v  = (float*)(sm + SM_B1);
    float* b2v  = (float*)(sm + SM_B2);
    float* sA   = (float*)(sm + SM_SA);
    float* sNX  = (float*)(sm + SM_SNX);
    float* sgA  = (float*)(sm + SM_SEGA);
    float* sgH  = (float*)(sm + SM_SEGH);
    float* hrun = (float*)(sm + SM_HRUN);
    float* prun = (float*)(sm + SM_PRUN);

    // inline weight conversion: fp32 [128k x 64n slice] -> fp16 swizzled smem
    #pragma unroll
    for (int g = 0; g < 2; g++) {
        const float* wsrc = (g ? w_a : w_in) + h * 16384 + half * 64;
        char* WH = sm + SM_W + g * 16384;
        for (int idx = tid; idx < 2048; idx += 256) {
            int k = idx >> 4, n4 = (idx & 15) * 4;
            float4 v = *(const float4*)&wsrc[k * 128 + n4];
            uint32_t off = swz128((uint32_t)k * 128u + (uint32_t)n4 * 2u);
            uint2 hp;
            hp.x = packh2(v.x, v.y); hp.y = packh2(v.z, v.w);
            *(uint2*)(WH + off) = hp;
        }
    }
    if (tid < 64) {
        int ch = col0 + tid;
        scv[tid] = 8.f * log1pf(expf(a_param[ch]));
        b1v[tid] = b_in[ch];
        b2v[tid] = b_a[ch];
    }
    if (tid < 32) {
        float2 z; z.x = 0.f; z.y = 0.f;
        float2 o; o.x = 1.f; o.y = 1.f;
        *(float2*)&hrun[tid * 2] = z;
        *(float2*)&prun[tid * 2] = o;
    }

    const int pr = tid >> 5, pc4 = (tid & 31) * 4;
    float4 xr[8];
    // load tile 0, stage into XH buffer 0 directly
    #pragma unroll
    for (int i = 0; i < 8; i++) {
        float4 v = *(const float4*)&x[(size_t)(row0 + pr + i * 8) * W_ + h * 128 + pc4];
        uint32_t off = swz256((uint32_t)(pr + i * 8) * 256u + (uint32_t)pc4 * 2u);
        uint2 hp;
        hp.x = packh2(v.x, v.y); hp.y = packh2(v.z, v.w);
        *(uint2*)(sm + SM_XH + off) = hp;
    }
    // prefetch tile 1
    #pragma unroll
    for (int i = 0; i < 8; i++)
        xr[i] = *(const float4*)&x[(size_t)(row0 + 64 + pr + i * 8) * W_ + h * 128 + pc4];
    __syncthreads();

    const uint32_t wbase = smem_u32(sm + SM_W);
    const uint32_t xh0   = smem_u32(sm + SM_XH);

    const int cw = wid >> 2, rw = wid & 3;
    const int mrow = rw * 16, ncol = cw * 32;
    const int cp  = lane * 2;
    const int seg = wid;

    for (int it = 0; it < ITERS; it++) {
        const int p = it & 1;
        const uint32_t xh_b = xh0 + p * 16384;         // shared addr for ldmatrix
        char* xh_ptr = sm + SM_XH + p * 16384;         // generic ptr for LDS

        // ---- mma: single-pass fp16, both gemms, warp tile 16x32 ----
        float C[2][4][4];
        #pragma unroll
        for (int g = 0; g < 2; g++)
            #pragma unroll
            for (int n = 0; n < 4; n++)
                #pragma unroll
                for (int e = 0; e < 4; e++) C[g][n][e] = 0.f;

        #pragma unroll
        for (int kt = 0; kt < 8; kt++) {
            const int k0 = kt * 16;
            uint32_t ah[4];
            {
                uint32_t off = swz256((uint32_t)(mrow + (lane & 15)) * 256u
                                      + (uint32_t)(k0 + (lane >> 4) * 8) * 2u);
                ldm_x4(ah, xh_b + off);
            }
            #pragma unroll
            for (int g = 0; g < 2; g++) {
                uint32_t bh[2][4];
                #pragma unroll
                for (int nn = 0; nn < 2; nn++) {
                    uint32_t off = swz128((uint32_t)(k0 + (lane & 15)) * 128u
                                          + (uint32_t)(ncol + nn * 16 + (lane >> 4) * 8) * 2u);
                    ldm_x4_t(bh[nn], wbase + g * 16384 + off);
                }
                #pragma unroll
                for (int n = 0; n < 4; n++)
                    mma_f16(C[g][n], ah, &bh[n >> 1][(n & 1) * 2]);
            }
        }

        // ---- epilogue: gates -> smem a/nx tiles (x values from XH[p]) ----
        #pragma unroll
        for (int hf = 0; hf < 2; hf++) {
            const int rloc = mrow + (lane >> 2) + hf * 8;
            const bool rst = (((row0 + it * 64 + rloc) & (T_ - 1)) == 0);
            #pragma unroll
            for (int n = 0; n < 4; n++) {
                const int col = ncol + n * 8 + (lane & 3) * 2;
                float v1a = C[0][n][hf * 2], v1b = C[0][n][hf * 2 + 1];
                float v2a = C[1][n][hf * 2], v2b = C[1][n][hf * 2 + 1];
                uint32_t xoff = swz256((uint32_t)rloc * 256u
                                       + (uint32_t)(half * 64 + col) * 2u);
                __half2 xhp = *(__half2*)(xh_ptr + xoff);
                float x0 = __half2float(xhp.x);
                float x1 = __half2float(xhp.y);
                float gx0 = sigm(v1a + b1v[col]),     gx1 = sigm(v1b + b1v[col + 1]);
                float ga0 = sigm(v2a + b2v[col]),     ga1 = sigm(v2b + b2v[col + 1]);
                float a0 = __expf(-scv[col] * ga0);
                float a1 = __expf(-scv[col + 1] * ga1);
                float m0 = sqrt_ap(fmaxf(0.f, 1.f - a0 * a0));
                float m1 = sqrt_ap(fmaxf(0.f, 1.f - a1 * a1));
                if (rst) { a0 = 0.f; a1 = 0.f; m0 = 1.f; m1 = 1.f; }
                float2 av; av.x = a0; av.y = a1;
                float2 nv; nv.x = x0 * gx0 * m0; nv.y = x1 * gx1 * m1;
                *(float2*)&sA [rloc * SP + col] = av;
                *(float2*)&sNX[rloc * SP + col] = nv;
            }
        }
        __syncthreads();                                   // [A]

        // ---- phase1: stage next XH, prefetch, register scan, seg summaries ----
        if (it < ITERS - 1) {
            char* xh_nxt = sm + SM_XH + (p ^ 1) * 16384;
            #pragma unroll
            for (int i = 0; i < 8; i++) {
                float4 v = xr[i];
                uint32_t off = swz256((uint32_t)(pr + i * 8) * 256u + (uint32_t)pc4 * 2u);
                uint2 hp;
                hp.x = packh2(v.x, v.y); hp.y = packh2(v.z, v.w);
                *(uint2*)(xh_nxt + off) = hp;
            }
            if (it < ITERS - 2) {
                #pragma unroll
                for (int i = 0; i < 8; i++)
                    xr[i] = *(const float4*)&x[(size_t)(row0 + (it + 2) * 64 + pr + i * 8) * W_ + h * 128 + pc4];
            }
        }

        float2 yl[8], pl[8];
        float2 hv; hv.x = 0.f; hv.y = 0.f;
        float2 pv; pv.x = 1.f; pv.y = 1.f;
        const int t0 = seg * 8;
        #pragma unroll
        for (int t = 0; t < 8; t++) {
            float2 a  = *(float2*)&sA [(t0 + t) * SP + cp];
            float2 nx = *(float2*)&sNX[(t0 + t) * SP + cp];
            hv.x = fmaf(a.x, hv.x, nx.x); hv.y = fmaf(a.y, hv.y, nx.y);
            pv.x *= a.x;                  pv.y *= a.y;
            yl[t] = hv; pl[t] = pv;
        }
        *(float2*)&sgA[seg * 64 + cp] = pv;
        *(float2*)&sgH[seg * 64 + cp] = hv;
        __syncthreads();                                   // [B]

        // ---- phase2+3: fold inbound carry, fix + store to gmem ----
        float2 cih = *(float2*)&hrun[p * 64 + cp];
        float2 cip = *(float2*)&prun[p * 64 + cp];
        for (int s = 0; s < seg; s++) {
            float2 A  = *(float2*)&sgA[s * 64 + cp];
            float2 Hh = *(float2*)&sgH[s * 64 + cp];
            cih.x = fmaf(A.x, cih.x, Hh.x); cih.y = fmaf(A.y, cih.y, Hh.y);
            cip.x *= A.x;                   cip.y *= A.y;
        }
        if (seg == 7) {
            float2 nh, np;
            nh.x = fmaf(pv.x, cih.x, hv.x); nh.y = fmaf(pv.y, cih.y, hv.y);
            np.x = cip.x * pv.x;            np.y = cip.y * pv.y;
            *(float2*)&hrun[(p ^ 1) * 64 + cp] = nh;
            *(float2*)&prun[(p ^ 1) * 64 + cp] = np;
        }
        {
            const size_t gtile = (size_t)(row0 + it * 64 + t0) * W_ + col0 + cp;
            if (c == 0) {
                #pragma unroll
                for (int t = 0; t < 8; t++) {
                    float2 yv;
                    yv.x = fmaf(pl[t].x, cih.x, yl[t].x);
                    yv.y = fmaf(pl[t].y, cih.y, yl[t].y);
                    *(float2*)&y[gtile + (size_t)t * W_] = yv;
                }
            } else {
                #pragma unroll
                for (int t = 0; t < 8; t++) {
                    __half2 Yv, Pv;
                    Yv.x = __float2half_rn(fmaf(pl[t].x, cih.x, yl[t].x));
                    Yv.y = __float2half_rn(fmaf(pl[t].y, cih.y, yl[t].y));
                    Pv.x = __float2half_rn(pl[t].x * cip.x);
                    Pv.y = __float2half_rn(pl[t].y * cip.y);
                    *(__half2*)&g_Ylh[gtile + (size_t)t * W_] = Yv;
                    *(__half2*)&g_Ph [gtile + (size_t)t * W_] = Pv;
                }
            }
        }
    }

    __syncthreads();
    if (tid < 32) {   // final carries live in parity 0 (ITERS even)
        int sidx = bx * W_ + col0 + cp;
        *(float2*)&g_hlast[sidx] = *(float2*)&hrun[cp];
        *(float2*)&g_Aprod[sidx] = *(float2*)&prun[cp];
    }
}

// ---------------- apply carries, write final fp32 y ----------------
__global__ void __launch_bounds__(1024) apply_kernel(float* __restrict__ y)
{
    const int sub  = blockIdx.x & 15;
    const int c    = (blockIdx.x >> 4) + 1;     // 1..3
    const int b    = blockIdx.y;
    const int pid  = threadIdx.x & 511;
    const int rpar = threadIdx.x >> 9;
    const int ch   = pid * 2;

    float2 carry; carry.x = 0.f; carry.y = 0.f;
    for (int s = 0; s < c; s++) {
        int sidx = (b * NCH + s) * W_ + ch;
        float2 A  = *(const float2*)&g_Aprod[sidx];
        float2 Hh = *(const float2*)&g_hlast[sidx];
        carry.x = fmaf(A.x, carry.x, Hh.x);
        carry.y = fmaf(A.y, carry.y, Hh.y);
    }

    size_t base = ((size_t)b * T_ + (size_t)c * CHL + (size_t)sub * 64 + rpar) * W_ + ch;
    #pragma unroll 8
    for (int t = 0; t < 32; t++) {
        size_t idx = base + (size_t)t * 2 * W_;
        __half2 Yl = *(const __half2*)&g_Ylh[idx];
        __half2 Ph = *(const __half2*)&g_Ph [idx];
        float2 yv;
        yv.x = fmaf(__half2float(Ph.x), carry.x, __half2float(Yl.x));
        yv.y = fmaf(__half2float(Ph.y), carry.y, __half2float(Yl.y));
        *(float2*)&y[idx] = yv;
    }
}

// ---------------------------------------------------------------------------
extern "C" void kernel_launch(void* const* d_in, const int* in_sizes, int n_in,
                              void* d_out, int out_size)
{
    const float* x       = (const float*)d_in[0];
    const float* w_in    = (const float*)d_in[1];
    const float* b_in    = (const float*)d_in[2];
    const float* w_a     = (const float*)d_in[3];
    const float* b_a     = (const float*)d_in[4];
    const float* a_param = (const float*)d_in[5];
    float* y = (float*)d_out;

    cudaFuncSetAttribute(gates_kernel,
                         cudaFuncAttributeMaxDynamicSharedMemorySize, SM_TOTAL);

    gates_kernel<<<dim3(B_ * NCH, H_ * 2), 256, SM_TOTAL>>>(x, w_in, b_in, w_a, b_a, a_param, y);
    apply_kernel<<<dim3((NCH - 1) * 16, B_), 1024>>>(y);
}

// round 15
// speedup vs baseline: 1.1060x; 1.1060x over previous
#include <cuda_runtime.h>
#include <cuda_fp16.h>
#include <cstdint>
#include <math.h>

#define B_   8
#define T_   4096
#define W_   1024
#define H_   8
#define NCH  4      // chunks per batch (1024 steps each)
#define CHL  1024
#define ITERS 16

// ---------------- scratch ----------------
__device__ __half g_Ph [(size_t)B_ * T_ * W_];   // chunk prefix products (fp16)
__device__ __half g_Ylh[(size_t)B_ * T_ * W_];   // chunk-local y (fp16, c>0 only)
__device__ float  g_Aprod[B_ * NCH * W_];
__device__ float  g_hlast[B_ * NCH * W_];

// ---------------- smem layout (bytes) ----------------
#define SM_W      0                         // 2 x 16384 (fp16 w1,w2 half-cols)
#define SM_XH     32768                     // 16384 (64 rows x 128 k fp16)
#define SM_AN     49152                     // 64*33*16 = 33792 (float4 {a0,a1,nx0,nx1})
#define SM_SC     82944                     // 256
#define SM_B1     83200
#define SM_B2     83456
#define SM_SEGA   83712                     // 8*64*4 = 2048
#define SM_SEGH   85760
#define SM_HRUN   87808                     // 2*64*4 parity
#define SM_PRUN   88320
#define SM_TOTAL  88832

__device__ __forceinline__ uint32_t smem_u32(const void* p) {
    uint32_t a;
    asm("{ .reg .u64 t; cvta.to.shared.u64 t, %1; cvt.u32.u64 %0, t; }" : "=r"(a) : "l"(p));
    return a;
}
__device__ __forceinline__ uint32_t swz256(uint32_t o) {
    return o ^ (((o >> 8) & 7u) << 4);
}
__device__ __forceinline__ uint32_t swz128(uint32_t o) {
    return o ^ ((o >> 3) & 0x70u);
}
__device__ __forceinline__ void ldm_x4(uint32_t* r, uint32_t addr) {
    asm volatile("ldmatrix.sync.aligned.m8n8.x4.shared.b16 {%0,%1,%2,%3}, [%4];"
        : "=r"(r[0]), "=r"(r[1]), "=r"(r[2]), "=r"(r[3]) : "r"(addr));
}
__device__ __forceinline__ void ldm_x4_t(uint32_t* r, uint32_t addr) {
    asm volatile("ldmatrix.sync.aligned.m8n8.x4.trans.shared.b16 {%0,%1,%2,%3}, [%4];"
        : "=r"(r[0]), "=r"(r[1]), "=r"(r[2]), "=r"(r[3]) : "r"(addr));
}
__device__ __forceinline__ void mma_f16(float* c, const uint32_t* a, const uint32_t* b) {
    asm volatile("mma.sync.aligned.m16n8k16.row.col.f32.f16.f16.f32 "
        "{%0,%1,%2,%3}, {%4,%5,%6,%7}, {%8,%9}, {%0,%1,%2,%3};"
        : "+f"(c[0]), "+f"(c[1]), "+f"(c[2]), "+f"(c[3])
        : "r"(a[0]), "r"(a[1]), "r"(a[2]), "r"(a[3]), "r"(b[0]), "r"(b[1]));
}
__device__ __forceinline__ float sigm(float v) {
    float t;
    asm("tanh.approx.f32 %0, %1;" : "=f"(t) : "f"(v * 0.5f));
    return fmaf(0.5f, t, 0.5f);
}
__device__ __forceinline__ float sqrt_ap(float v) {
    float r; asm("sqrt.approx.f32 %0, %1;" : "=f"(r) : "f"(v)); return r;
}
__device__ __forceinline__ uint32_t packh2(float a, float b) {
    __half2 t; t.x = __float2half_rn(a); t.y = __float2half_rn(b);
    return *(uint32_t*)&t;
}

// ---------------------------------------------------------------------------
// gates GEMM + fused scan. block = (chunk, head-half). 256 threads, 2 CTAs/SM.
// R12 structure (3 barriers/iter), combined float4 a/nx buffer.
// ---------------------------------------------------------------------------
__global__ void __launch_bounds__(256, 2) gates_kernel(
    const float* __restrict__ x, const float* __restrict__ w_in,
    const float* __restrict__ b_in, const float* __restrict__ w_a,
    const float* __restrict__ b_a, const float* __restrict__ a_param,
    float* __restrict__ y)
{
    extern __shared__ char sm[];
    const int tid = threadIdx.x, wid = tid >> 5, lane = tid & 31;
    const int h = blockIdx.y >> 1, half = blockIdx.y & 1;
    const int bx = blockIdx.x;                 // b*NCH + chunk
    const int c  = bx & (NCH - 1);
    const int row0 = bx * CHL;
    const int col0 = h * 128 + half * 64;

    float*  scv  = (float*)(sm + SM_SC);
    float*  b1v  = (float*)(sm + SM_B1);
    float*  b2v  = (float*)(sm + SM_B2);
    float4* sAN  = (float4*)(sm + SM_AN);      // [row][cpi] {a0,a1,nx0,nx1}, stride 33
    float*  sgA  = (float*)(sm + SM_SEGA);
    float*  sgH  = (float*)(sm + SM_SEGH);
    float*  hrun = (float*)(sm + SM_HRUN);
    float*  prun = (float*)(sm + SM_PRUN);

    // inline weight conversion: fp32 [128k x 64n slice] -> fp16 swizzled smem
    #pragma unroll
    for (int g = 0; g < 2; g++) {
        const float* wsrc = (g ? w_a : w_in) + h * 16384 + half * 64;
        char* WH = sm + SM_W + g * 16384;
        for (int idx = tid; idx < 2048; idx += 256) {
            int k = idx >> 4, n4 = (idx & 15) * 4;
            float4 v = *(const float4*)&wsrc[k * 128 + n4];
            uint32_t off = swz128((uint32_t)k * 128u + (uint32_t)n4 * 2u);
            uint2 hp;
            hp.x = packh2(v.x, v.y); hp.y = packh2(v.z, v.w);
            *(uint2*)(WH + off) = hp;
        }
    }
    if (tid < 64) {
        int ch = col0 + tid;
        scv[tid] = 8.f * log1pf(expf(a_param[ch]));
        b1v[tid] = b_in[ch];
        b2v[tid] = b_a[ch];
    }
    if (tid < 32) {
        float2 z; z.x = 0.f; z.y = 0.f;
        float2 o; o.x = 1.f; o.y = 1.f;
        *(float2*)&hrun[tid * 2] = z;
        *(float2*)&prun[tid * 2] = o;
    }

    const int pr = tid >> 5, pc4 = (tid & 31) * 4;
    float4 xr[8];
    #pragma unroll
    for (int i = 0; i < 8; i++)
        xr[i] = *(const float4*)&x[(size_t)(row0 + pr + i * 8) * W_ + h * 128 + pc4];
    __syncthreads();

    const uint32_t xh_b  = smem_u32(sm + SM_XH);
    const uint32_t wbase = smem_u32(sm + SM_W);

    const int cw = wid >> 2, rw = wid & 3;
    const int mrow = rw * 16, ncol = cw * 32;
    const int cp  = lane * 2;
    const int seg = wid;

    for (int it = 0; it < ITERS; it++) {
        const int p = it & 1;
        // ---- stage x -> smem fp16 (swizzled 256B rows) ----
        #pragma unroll
        for (int i = 0; i < 8; i++) {
            float4 v = xr[i];
            uint32_t off = swz256((uint32_t)(pr + i * 8) * 256u + (uint32_t)pc4 * 2u);
            uint2 hp;
            hp.x = packh2(v.x, v.y); hp.y = packh2(v.z, v.w);
            *(uint2*)(sm + SM_XH + off) = hp;
        }
        __syncthreads();

        if (it < ITERS - 1) {
            #pragma unroll
            for (int i = 0; i < 8; i++)
                xr[i] = *(const float4*)&x[(size_t)(row0 + (it + 1) * 64 + pr + i * 8) * W_ + h * 128 + pc4];
        }

        // ---- mma: single-pass fp16, both gemms, warp tile 16x32 ----
        float C[2][4][4];
        #pragma unroll
        for (int g = 0; g < 2; g++)
            #pragma unroll
            for (int n = 0; n < 4; n++)
                #pragma unroll
                for (int e = 0; e < 4; e++) C[g][n][e] = 0.f;

        #pragma unroll
        for (int kt = 0; kt < 8; kt++) {
            const int k0 = kt * 16;
            uint32_t ah[4];
            {
                uint32_t off = swz256((uint32_t)(mrow + (lane & 15)) * 256u
                                      + (uint32_t)(k0 + (lane >> 4) * 8) * 2u);
                ldm_x4(ah, xh_b + off);
            }
            #pragma unroll
            for (int g = 0; g < 2; g++) {
                uint32_t bh[2][4];
                #pragma unroll
                for (int nn = 0; nn < 2; nn++) {
                    uint32_t off = swz128((uint32_t)(k0 + (lane & 15)) * 128u
                                          + (uint32_t)(ncol + nn * 16 + (lane >> 4) * 8) * 2u);
                    ldm_x4_t(bh[nn], wbase + g * 16384 + off);
                }
                #pragma unroll
                for (int n = 0; n < 4; n++)
                    mma_f16(C[g][n], ah, &bh[n >> 1][(n & 1) * 2]);
            }
        }

        // ---- epilogue: gates -> combined smem a/nx float4 tile ----
        #pragma unroll
        for (int hf = 0; hf < 2; hf++) {
            const int rloc = mrow + (lane >> 2) + hf * 8;
            const bool rst = (((row0 + it * 64 + rloc) & (T_ - 1)) == 0);
            #pragma unroll
            for (int n = 0; n < 4; n++) {
                const int col = ncol + n * 8 + (lane & 3) * 2;
                float v1a = C[0][n][hf * 2], v1b = C[0][n][hf * 2 + 1];
                float v2a = C[1][n][hf * 2], v2b = C[1][n][hf * 2 + 1];
                uint32_t xoff = swz256((uint32_t)rloc * 256u
                                       + (uint32_t)(half * 64 + col) * 2u);
                __half2 xhp = *(__half2*)(sm + SM_XH + xoff);
                float x0 = __half2float(xhp.x);
                float x1 = __half2float(xhp.y);
                float gx0 = sigm(v1a + b1v[col]),     gx1 = sigm(v1b + b1v[col + 1]);
                float ga0 = sigm(v2a + b2v[col]),     ga1 = sigm(v2b + b2v[col + 1]);
                float a0 = __expf(-scv[col] * ga0);
                float a1 = __expf(-scv[col + 1] * ga1);
                float m0 = sqrt_ap(fmaxf(0.f, 1.f - a0 * a0));
                float m1 = sqrt_ap(fmaxf(0.f, 1.f - a1 * a1));
                if (rst) { a0 = 0.f; a1 = 0.f; m0 = 1.f; m1 = 1.f; }
                float4 q;
                q.x = a0; q.y = a1;
                q.z = x0 * gx0 * m0; q.w = x1 * gx1 * m1;
                sAN[rloc * 33 + (col >> 1)] = q;
            }
        }
        __syncthreads();

        // ---- phase 1: 8-step register scan (warp = seg, lane = chan pair) ----
        float2 yl[8], pl[8];
        float2 hv; hv.x = 0.f; hv.y = 0.f;
        float2 pv; pv.x = 1.f; pv.y = 1.f;
        const int t0 = seg * 8;
        #pragma unroll
        for (int t = 0; t < 8; t++) {
            float4 q = sAN[(t0 + t) * 33 + lane];
            hv.x = fmaf(q.x, hv.x, q.z); hv.y = fmaf(q.y, hv.y, q.w);
            pv.x *= q.x;                 pv.y *= q.y;
            yl[t] = hv; pl[t] = pv;
        }
        *(float2*)&sgA[seg * 64 + cp] = pv;
        *(float2*)&sgH[seg * 64 + cp] = hv;
        __syncthreads();

        // ---- phase 2+3: fold inbound carry, fix + store to gmem ----
        float2 cih = *(float2*)&hrun[p * 64 + cp];
        float2 cip = *(float2*)&prun[p * 64 + cp];
        for (int s = 0; s < seg; s++) {
            float2 A  = *(float2*)&sgA[s * 64 + cp];
            float2 Hh = *(float2*)&sgH[s * 64 + cp];
            cih.x = fmaf(A.x, cih.x, Hh.x); cih.y = fmaf(A.y, cih.y, Hh.y);
            cip.x *= A.x;                   cip.y *= A.y;
        }
        if (seg == 7) {
            float2 nh, np;
            nh.x = fmaf(pv.x, cih.x, hv.x); nh.y = fmaf(pv.y, cih.y, hv.y);
            np.x = cip.x * pv.x;            np.y = cip.y * pv.y;
            *(float2*)&hrun[(p ^ 1) * 64 + cp] = nh;
            *(float2*)&prun[(p ^ 1) * 64 + cp] = np;
        }
        {
            const size_t gtile = (size_t)(row0 + it * 64 + t0) * W_ + col0 + cp;
            if (c == 0) {
                #pragma unroll
                for (int t = 0; t < 8; t++) {
                    float2 yv;
                    yv.x = fmaf(pl[t].x, cih.x, yl[t].x);
                    yv.y = fmaf(pl[t].y, cih.y, yl[t].y);
                    *(float2*)&y[gtile + (size_t)t * W_] = yv;
                }
            } else {
                #pragma unroll
                for (int t = 0; t < 8; t++) {
                    __half2 Yv, Pv;
                    Yv.x = __float2half_rn(fmaf(pl[t].x, cih.x, yl[t].x));
                    Yv.y = __float2half_rn(fmaf(pl[t].y, cih.y, yl[t].y));
                    Pv.x = __float2half_rn(pl[t].x * cip.x);
                    Pv.y = __float2half_rn(pl[t].y * cip.y);
                    *(__half2*)&g_Ylh[gtile + (size_t)t * W_] = Yv;
                    *(__half2*)&g_Ph [gtile + (size_t)t * W_] = Pv;
                }
            }
        }
    }

    __syncthreads();
    if (tid < 32) {   // final carries live in parity 0 (ITERS even)
        int sidx = bx * W_ + col0 + cp;
        *(float2*)&g_hlast[sidx] = *(float2*)&hrun[cp];
        *(float2*)&g_Aprod[sidx] = *(float2*)&prun[cp];
    }
}

// ---------------- apply carries, write final fp32 y ----------------
__global__ void __launch_bounds__(1024) apply_kernel(float* __restrict__ y)
{
    const int sub  = blockIdx.x & 15;
    const int c    = (blockIdx.x >> 4) + 1;     // 1..3
    const int b    = blockIdx.y;
    const int pid  = threadIdx.x & 511;
    const int rpar = threadIdx.x >> 9;
    const int ch   = pid * 2;

    float2 carry; carry.x = 0.f; carry.y = 0.f;
    for (int s = 0; s < c; s++) {
        int sidx = (b * NCH + s) * W_ + ch;
        float2 A  = *(const float2*)&g_Aprod[sidx];
        float2 Hh = *(const float2*)&g_hlast[sidx];
        carry.x = fmaf(A.x, carry.x, Hh.x);
        carry.y = fmaf(A.y, carry.y, Hh.y);
    }

    size_t base = ((size_t)b * T_ + (size_t)c * CHL + (size_t)sub * 64 + rpar) * W_ + ch;
    #pragma unroll 8
    for (int t = 0; t < 32; t++) {
        size_t idx = base + (size_t)t * 2 * W_;
        __half2 Yl = *(const __half2*)&g_Ylh[idx];
        __half2 Ph = *(const __half2*)&g_Ph [idx];
        float2 yv;
        yv.x = fmaf(__half2float(Ph.x), carry.x, __half2float(Yl.x));
        yv.y = fmaf(__half2float(Ph.y), carry.y, __half2float(Yl.y));
        *(float2*)&y[idx] = yv;
    }
}

// ---------------------------------------------------------------------------
extern "C" void kernel_launch(void* const* d_in, const int* in_sizes, int n_in,
                              void* d_out, int out_size)
{
    const float* x       = (const float*)d_in[0];
    const float* w_in    = (const float*)d_in[1];
    const float* b_in    = (const float*)d_in[2];
    const float* w_a     = (const float*)d_in[3];
    const float* b_a     = (const float*)d_in[4];
    const float* a_param = (const float*)d_in[5];
    float* y = (float*)d_out;

    cudaFuncSetAttribute(gates_kernel,
                         cudaFuncAttributeMaxDynamicSharedMemorySize, SM_TOTAL);

    gates_kernel<<<dim3(B_ * NCH, H_ * 2), 256, SM_TOTAL>>>(x, w_in, b_in, w_a, b_a, a_param, y);
    apply_kernel<<<dim3((NCH - 1) * 16, B_), 1024>>>(y);
}